// round 11
// baseline (speedup 1.0000x reference)
#include <cuda_runtime.h>
#include <cuda_fp16.h>
#include <cuda_fp8.h>
#include <cstdint>

#define D 512
#define NMAX 8192
#define KC 128                        // K bytes per stage (fp8 elems)
#define STAGE 32768                   // A:128*128B + B:128*128B
#define NSTG 3
#define NCHUNK 4                      // 512 / 128
#define DYN_SMEM (NSTG * STAGE + 1024)
#define QS 16.0f                      // quantization pre-scale
#define LSCALE 0.0078125f             // logits = dot * tau_inv / QS^2 = dot/128

// Scratch (no device allocations allowed)
__device__ uint8_t g_x8[(size_t)NMAX * D];
__device__ uint8_t g_y8[(size_t)NMAX * D];
__device__ float g_rowsum[NMAX];
__device__ float g_colsum[NMAX];
__device__ float g_diag;
__device__ unsigned int g_cnt;

// ---------------------------------------------------------------------------
__device__ __forceinline__ uint32_t smem_u32(const void* p) {
    uint32_t r;
    asm("{ .reg .u64 t; cvta.to.shared.u64 t, %1; cvt.u32.u64 %0, t; }"
        : "=r"(r) : "l"(p));
    return r;
}
__device__ __forceinline__ void cp16(uint32_t s, const void* g) {
    asm volatile("cp.async.cg.shared.global [%0], [%1], 16;\n" :: "r"(s), "l"(g));
}
__device__ __forceinline__ uint32_t sw(uint32_t off) {   // SW128 XOR swizzle
    return off ^ ((off >> 3) & 0x70);
}
__device__ __forceinline__ void ldm4(uint32_t* r, uint32_t s) {
    asm volatile("ldmatrix.sync.aligned.m8n8.x4.shared.b16 {%0,%1,%2,%3}, [%4];\n"
                 : "=r"(r[0]), "=r"(r[1]), "=r"(r[2]), "=r"(r[3]) : "r"(s));
}
// fp8 e4m3 MMA with f16 accumulators: D/C are 2 regs of packed half2
__device__ __forceinline__ void mma_fp8h(uint32_t* c, const uint32_t* a,
                                         const uint32_t* b) {
    asm volatile("mma.sync.aligned.m16n8k32.row.col.f16.e4m3.e4m3.f16 "
                 "{%0,%1}, {%2,%3,%4,%5}, {%6,%7}, {%0,%1};\n"
                 : "+r"(c[0]), "+r"(c[1])
                 : "r"(a[0]), "r"(a[1]), "r"(a[2]), "r"(a[3]),
                   "r"(b[0]), "r"(b[1]));
}

// ---------------------------------------------------------------------------
// normalize -> scale by QS -> e4m3. TWO rows per warp, loads batched for MLP.
// Fused accumulator zeroing.
__global__ void normalize_kernel(const float* __restrict__ x,
                                 const float* __restrict__ y, int n) {
    int gw = (blockIdx.x * blockDim.x + threadIdx.x) >> 5;   // warp id
    int lane = threadIdx.x & 31;
    int r0 = 2 * gw, r1 = 2 * gw + 1;                        // rows in [0, 2n)
    if (r0 >= 2 * n) return;

    if (lane == 0) {
        if (r0 < n) { g_rowsum[r0] = 0.f; g_colsum[r0] = 0.f; }
        if (r1 < n) { g_rowsum[r1] = 0.f; g_colsum[r1] = 0.f; }
        if (r0 == 0) { g_diag = 0.f; g_cnt = 0u; }
    }
    // pairs never straddle the x/y boundary (n even, r0 even)
    const float* src = (r0 < n) ? x : y;
    uint8_t* dst = (r0 < n) ? g_x8 : g_y8;
    int rr0 = (r0 < n) ? r0 : r0 - n;

    const float4* p0 = (const float4*)(src + (size_t)rr0 * D);
    const float4* p1 = (const float4*)(src + (size_t)(rr0 + 1) * D);
    float4 v0[4], v1[4];
    #pragma unroll
    for (int i = 0; i < 4; i++) v0[i] = p0[lane + 32 * i];
    #pragma unroll
    for (int i = 0; i < 4; i++) v1[i] = p1[lane + 32 * i];

    float s0 = 0.f, s1 = 0.f;
    #pragma unroll
    for (int i = 0; i < 4; i++) {
        s0 += v0[i].x*v0[i].x + v0[i].y*v0[i].y + v0[i].z*v0[i].z + v0[i].w*v0[i].w;
        s1 += v1[i].x*v1[i].x + v1[i].y*v1[i].y + v1[i].z*v1[i].z + v1[i].w*v1[i].w;
    }
    #pragma unroll
    for (int o = 16; o; o >>= 1) {
        s0 += __shfl_xor_sync(0xffffffffu, s0, o);
        s1 += __shfl_xor_sync(0xffffffffu, s1, o);
    }
    float q0 = QS / fmaxf(sqrtf(s0), 1e-8f);
    float q1 = QS / fmaxf(sqrtf(s1), 1e-8f);

    uint32_t* d0 = (uint32_t*)(dst + (size_t)rr0 * D);
    uint32_t* d1 = (uint32_t*)(dst + (size_t)(rr0 + 1) * D);
    #pragma unroll
    for (int i = 0; i < 4; i++) {
        __nv_fp8x2_storage_t a = __nv_cvt_float2_to_fp8x2(
            make_float2(v0[i].x * q0, v0[i].y * q0), __NV_SATFINITE, __NV_E4M3);
        __nv_fp8x2_storage_t b = __nv_cvt_float2_to_fp8x2(
            make_float2(v0[i].z * q0, v0[i].w * q0), __NV_SATFINITE, __NV_E4M3);
        d0[lane + 32 * i] = (uint32_t)a | ((uint32_t)b << 16);
        __nv_fp8x2_storage_t c = __nv_cvt_float2_to_fp8x2(
            make_float2(v1[i].x * q1, v1[i].y * q1), __NV_SATFINITE, __NV_E4M3);
        __nv_fp8x2_storage_t e = __nv_cvt_float2_to_fp8x2(
            make_float2(v1[i].z * q1, v1[i].w * q1), __NV_SATFINITE, __NV_E4M3);
        d1[lane + 32 * i] = (uint32_t)c | ((uint32_t)e << 16);
    }
}

// ---------------------------------------------------------------------------
// 128(M) x 128(N) tile per CTA, 8 warps 4(M) x 2(N), warp tile 32x64.
// fp8 e4m3 k32 MMA, f16 accumulators -> 2 CTAs/SM (epilogue overlaps MMA).
// Fused streaming-softmax epilogue + last-block finalize.
__global__ void __launch_bounds__(256, 2) gemm_kernel(float* __restrict__ out,
                                                      int n) {
    extern __shared__ char dyn_raw[];
    __shared__ unsigned int s_last;
    const int tid = threadIdx.x, lane = tid & 31, wid = tid >> 5;
    const int wm = wid & 3, wn = wid >> 2;
    const int bi = blockIdx.y, bj = blockIdx.x;
    const int g = lane >> 3, rr = lane & 7;

    uint32_t dynb = (smem_u32(dyn_raw) + 1023u) & ~1023u;

    const uint8_t* Ag = g_x8 + (size_t)bi * 128 * D;
    const uint8_t* Bg = g_y8 + (size_t)bj * 128 * D;

    auto issue = [&](int kc, uint32_t stage) {
        #pragma unroll
        for (int it = 0; it < 4; it++) {                  // A: 128 rows x 8 segs
            int i = tid + it * 256; int r = i >> 3, j = i & 7;
            uint32_t off = (uint32_t)(r * 128 + j * 16);
            cp16(stage + sw(off), Ag + r * D + kc * KC + j * 16);
        }
        #pragma unroll
        for (int it = 0; it < 4; it++) {                  // B: 128 rows x 8 segs
            int i = tid + it * 256; int r = i >> 3, j = i & 7;
            uint32_t off = (uint32_t)(r * 128 + j * 16);
            cp16(stage + 16384 + sw(off), Bg + r * D + kc * KC + j * 16);
        }
        asm volatile("cp.async.commit_group;");
    };

    issue(0, dynb);
    issue(1, dynb + STAGE);

    uint32_t acc[2][8][2];                                // packed half2 x2
    #pragma unroll
    for (int i = 0; i < 2; i++)
        #pragma unroll
        for (int j = 0; j < 8; j++) { acc[i][j][0] = 0u; acc[i][j][1] = 0u; }

    for (int kc = 0; kc < NCHUNK; kc++) {
        if (kc < NCHUNK - 2) asm volatile("cp.async.wait_group 1;");
        else                 asm volatile("cp.async.wait_group 0;");
        __syncthreads();
        if (kc + 2 < NCHUNK)
            issue(kc + 2, dynb + ((kc + 2) % 3) * STAGE);

        uint32_t sA = dynb + (kc % 3) * STAGE;
        uint32_t sB = sA + 16384;

        #pragma unroll
        for (int ks = 0; ks < 4; ks++) {
            const int k0 = ks * 32;                       // byte offset in row
            uint32_t a[2][4];
            #pragma unroll
            for (int mt = 0; mt < 2; mt++) {
                int arow = wm * 32 + mt * 16 + (g & 1) * 8 + rr;
                int acol = k0 + (g >> 1) * 16;
                ldm4(a[mt], sA + sw((uint32_t)(arow * 128 + acol)));
            }
            uint32_t b[8][2];
            #pragma unroll
            for (int ntp = 0; ntp < 4; ntp++) {
                int brow = wn * 64 + ntp * 16 + (g & 1) * 8 + rr;
                int bcol = k0 + (g >> 1) * 16;
                uint32_t t[4];
                ldm4(t, sB + sw((uint32_t)(brow * 128 + bcol)));
                b[2 * ntp][0] = t[0];     b[2 * ntp + 1][0] = t[1];
                b[2 * ntp][1] = t[2];     b[2 * ntp + 1][1] = t[3];
            }
            #pragma unroll
            for (int mt = 0; mt < 2; mt++)
                #pragma unroll
                for (int nt = 0; nt < 8; nt++)
                    mma_fp8h(acc[mt][nt], a[mt], b[nt]);
        }
    }

    // ---- fused epilogue: logits = dot/128; streaming exp-sums ----
    const bool hasdiag = (bi == bj);
    const int mrow_loc = wm * 32 + (lane >> 2);
    const int ncol_loc = wn * 64 + 2 * (lane & 3);

    float rsum[2][2];
    rsum[0][0] = rsum[0][1] = rsum[1][0] = rsum[1][1] = 0.f;
    float dsum = 0.f;

    #pragma unroll
    for (int nt = 0; nt < 8; nt++) {
        float cs0 = 0.f, cs1 = 0.f;
        #pragma unroll
        for (int mt = 0; mt < 2; mt++) {
            float2 c01 = __half22float2(*(__half2*)&acc[mt][nt][0]);
            float2 c23 = __half22float2(*(__half2*)&acc[mt][nt][1]);
            float l00 = LSCALE * c01.x, l01 = LSCALE * c01.y;
            float l10 = LSCALE * c23.x, l11 = LSCALE * c23.y;
            float e00 = __expf(l00), e01 = __expf(l01);
            float e10 = __expf(l10), e11 = __expf(l11);
            rsum[mt][0] += e00 + e01;
            rsum[mt][1] += e10 + e11;
            cs0 += e00 + e10;
            cs1 += e01 + e11;
            if (hasdiag) {
                int m0 = mrow_loc + mt * 16;
                int n0 = ncol_loc + nt * 8;
                if (m0 == n0)         dsum += l00;
                if (m0 == n0 + 1)     dsum += l01;
                if (m0 + 8 == n0)     dsum += l10;
                if (m0 + 8 == n0 + 1) dsum += l11;
            }
        }
        #pragma unroll
        for (int o = 4; o < 32; o <<= 1) {
            cs0 += __shfl_xor_sync(0xffffffffu, cs0, o);
            cs1 += __shfl_xor_sync(0xffffffffu, cs1, o);
        }
        if (lane < 4) {
            int col = bj * 128 + wn * 64 + nt * 8 + 2 * lane;
            atomicAdd(&g_colsum[col],     cs0);
            atomicAdd(&g_colsum[col + 1], cs1);
        }
    }
    #pragma unroll
    for (int mt = 0; mt < 2; mt++) {
        #pragma unroll
        for (int h = 0; h < 2; h++) {
            float v = rsum[mt][h];
            v += __shfl_xor_sync(0xffffffffu, v, 1);
            v += __shfl_xor_sync(0xffffffffu, v, 2);
            if ((lane & 3) == 0) {
                int row = bi * 128 + wm * 32 + mt * 16 + h * 8 + (lane >> 2);
                atomicAdd(&g_rowsum[row], v);
            }
        }
    }
    if (hasdiag) {
        #pragma unroll
        for (int o = 16; o; o >>= 1) dsum += __shfl_xor_sync(0xffffffffu, dsum, o);
        if (lane == 0) atomicAdd(&g_diag, dsum);
    }

    // ---- last-block finalize ----
    __threadfence();
    __syncthreads();
    if (tid == 0) {
        unsigned total = gridDim.x * gridDim.y;
        s_last = (atomicAdd(&g_cnt, 1u) == total - 1) ? 1u : 0u;
    }
    __syncthreads();
    if (s_last) {
        float s = 0.f;
        for (int i = tid; i < n; i += 256)
            s += logf(__ldcg(&g_rowsum[i])) + logf(__ldcg(&g_colsum[i]));
        #pragma unroll
        for (int o = 16; o; o >>= 1) s += __shfl_xor_sync(0xffffffffu, s, o);
        __shared__ float red[8];
        if (lane == 0) red[wid] = s;
        __syncthreads();
        if (tid == 0) {
            float v = 0.f;
            #pragma unroll
            for (int w = 0; w < 8; w++) v += red[w];
            out[0] = v / (2.f * (float)n) - __ldcg(&g_diag) / (float)n;
        }
    }
}

// ---------------------------------------------------------------------------
extern "C" void kernel_launch(void* const* d_in, const int* in_sizes, int n_in,
                              void* d_out, int out_size) {
    const float* x = (const float*)d_in[0];
    const float* y = (const float*)d_in[1];
    int n = in_sizes[0] / D;   // 8192

    cudaFuncSetAttribute(gemm_kernel,
                         cudaFuncAttributeMaxDynamicSharedMemorySize, DYN_SMEM);

    normalize_kernel<<<(2 * n) / 16, 256>>>(x, y, n);  // 2 rows per warp
    gemm_kernel<<<dim3(n / 128, n / 128), 256, DYN_SMEM>>>((float*)d_out, n);
}

// round 12
// speedup vs baseline: 1.1572x; 1.1572x over previous
#include <cuda_runtime.h>
#include <cuda_fp16.h>
#include <cuda_fp8.h>
#include <cstdint>

#define D 512
#define NMAX 8192
#define KC 128                        // K bytes per stage (fp8 elems)
#define STAGE 32768                   // A:128*128B + B:128*128B
#define NSTG 2
#define NCHUNK 4                      // 512 / 128
#define DYN_SMEM (NSTG * STAGE + 1024)
#define QS 16.0f                      // quantization pre-scale
#define LSCALE 0.0078125f             // logits = dot * tau_inv / QS^2 = dot/128

// Scratch (no device allocations allowed)
__device__ uint8_t g_x8[(size_t)NMAX * D];
__device__ uint8_t g_y8[(size_t)NMAX * D];
__device__ float g_rowsum[NMAX];
__device__ float g_colsum[NMAX];
__device__ float g_diag;
__device__ float g_part;
__device__ unsigned int g_cnt;

// ---------------------------------------------------------------------------
__device__ __forceinline__ uint32_t smem_u32(const void* p) {
    uint32_t r;
    asm("{ .reg .u64 t; cvta.to.shared.u64 t, %1; cvt.u32.u64 %0, t; }"
        : "=r"(r) : "l"(p));
    return r;
}
__device__ __forceinline__ void cp16(uint32_t s, const void* g) {
    asm volatile("cp.async.cg.shared.global [%0], [%1], 16;\n" :: "r"(s), "l"(g));
}
__device__ __forceinline__ uint32_t sw(uint32_t off) {   // SW128 XOR swizzle
    return off ^ ((off >> 3) & 0x70);
}
__device__ __forceinline__ void ldm4(uint32_t* r, uint32_t s) {
    asm volatile("ldmatrix.sync.aligned.m8n8.x4.shared.b16 {%0,%1,%2,%3}, [%4];\n"
                 : "=r"(r[0]), "=r"(r[1]), "=r"(r[2]), "=r"(r[3]) : "r"(s));
}
// fp8 e4m3 MMA with f16 accumulators: D/C are 2 regs of packed half2
__device__ __forceinline__ void mma_fp8h(uint32_t* c, const uint32_t* a,
                                         const uint32_t* b) {
    asm volatile("mma.sync.aligned.m16n8k32.row.col.f16.e4m3.e4m3.f16 "
                 "{%0,%1}, {%2,%3,%4,%5}, {%6,%7}, {%0,%1};\n"
                 : "+r"(c[0]), "+r"(c[1])
                 : "r"(a[0]), "r"(a[1]), "r"(a[2]), "r"(a[3]),
                   "r"(b[0]), "r"(b[1]));
}

// ---------------------------------------------------------------------------
// normalize -> scale by QS -> e4m3. TWO rows per warp, loads batched for MLP.
// Fused accumulator zeroing.
__global__ void normalize_kernel(const float* __restrict__ x,
                                 const float* __restrict__ y, int n) {
    int gw = (blockIdx.x * blockDim.x + threadIdx.x) >> 5;   // warp id
    int lane = threadIdx.x & 31;
    int r0 = 2 * gw, r1 = 2 * gw + 1;
    if (r0 >= 2 * n) return;

    if (lane == 0) {
        if (r0 < n) { g_rowsum[r0] = 0.f; g_colsum[r0] = 0.f; }
        if (r1 < n) { g_rowsum[r1] = 0.f; g_colsum[r1] = 0.f; }
        if (r0 == 0) { g_diag = 0.f; g_part = 0.f; g_cnt = 0u; }
    }
    const float* src = (r0 < n) ? x : y;
    uint8_t* dst = (r0 < n) ? g_x8 : g_y8;
    int rr0 = (r0 < n) ? r0 : r0 - n;

    const float4* p0 = (const float4*)(src + (size_t)rr0 * D);
    const float4* p1 = (const float4*)(src + (size_t)(rr0 + 1) * D);
    float4 v0[4], v1[4];
    #pragma unroll
    for (int i = 0; i < 4; i++) v0[i] = p0[lane + 32 * i];
    #pragma unroll
    for (int i = 0; i < 4; i++) v1[i] = p1[lane + 32 * i];

    float s0 = 0.f, s1 = 0.f;
    #pragma unroll
    for (int i = 0; i < 4; i++) {
        s0 += v0[i].x*v0[i].x + v0[i].y*v0[i].y + v0[i].z*v0[i].z + v0[i].w*v0[i].w;
        s1 += v1[i].x*v1[i].x + v1[i].y*v1[i].y + v1[i].z*v1[i].z + v1[i].w*v1[i].w;
    }
    #pragma unroll
    for (int o = 16; o; o >>= 1) {
        s0 += __shfl_xor_sync(0xffffffffu, s0, o);
        s1 += __shfl_xor_sync(0xffffffffu, s1, o);
    }
    float q0 = QS / fmaxf(sqrtf(s0), 1e-8f);
    float q1 = QS / fmaxf(sqrtf(s1), 1e-8f);

    uint32_t* d0 = (uint32_t*)(dst + (size_t)rr0 * D);
    uint32_t* d1 = (uint32_t*)(dst + (size_t)(rr0 + 1) * D);
    #pragma unroll
    for (int i = 0; i < 4; i++) {
        __nv_fp8x2_storage_t a = __nv_cvt_float2_to_fp8x2(
            make_float2(v0[i].x * q0, v0[i].y * q0), __NV_SATFINITE, __NV_E4M3);
        __nv_fp8x2_storage_t b = __nv_cvt_float2_to_fp8x2(
            make_float2(v0[i].z * q0, v0[i].w * q0), __NV_SATFINITE, __NV_E4M3);
        d0[lane + 32 * i] = (uint32_t)a | ((uint32_t)b << 16);
        __nv_fp8x2_storage_t c = __nv_cvt_float2_to_fp8x2(
            make_float2(v1[i].x * q1, v1[i].y * q1), __NV_SATFINITE, __NV_E4M3);
        __nv_fp8x2_storage_t e = __nv_cvt_float2_to_fp8x2(
            make_float2(v1[i].z * q1, v1[i].w * q1), __NV_SATFINITE, __NV_E4M3);
        d1[lane + 32 * i] = (uint32_t)c | ((uint32_t)e << 16);
    }
}

// ---------------------------------------------------------------------------
// 128(M) x 128(N) tile per CTA, 8 warps 4(M) x 2(N), warp tile 32x64.
// fp8 e4m3 k32 MMA, f16 accumulators. 2-stage pipeline, 65KB smem ->
// 3 CTAs/SM: cross-CTA overlap hides barriers, loads and epilogue.
__global__ void __launch_bounds__(256, 3) gemm_kernel() {
    extern __shared__ char dyn_raw[];
    const int tid = threadIdx.x, lane = tid & 31, wid = tid >> 5;
    const int wm = wid & 3, wn = wid >> 2;
    const int bi = blockIdx.y, bj = blockIdx.x;
    const int g = lane >> 3, rr = lane & 7;

    uint32_t dynb = (smem_u32(dyn_raw) + 1023u) & ~1023u;

    const uint8_t* Ag = g_x8 + (size_t)bi * 128 * D;
    const uint8_t* Bg = g_y8 + (size_t)bj * 128 * D;

    auto issue = [&](int kc, uint32_t stage) {
        #pragma unroll
        for (int it = 0; it < 4; it++) {                  // A: 128 rows x 8 segs
            int i = tid + it * 256; int r = i >> 3, j = i & 7;
            uint32_t off = (uint32_t)(r * 128 + j * 16);
            cp16(stage + sw(off), Ag + r * D + kc * KC + j * 16);
        }
        #pragma unroll
        for (int it = 0; it < 4; it++) {                  // B: 128 rows x 8 segs
            int i = tid + it * 256; int r = i >> 3, j = i & 7;
            uint32_t off = (uint32_t)(r * 128 + j * 16);
            cp16(stage + 16384 + sw(off), Bg + r * D + kc * KC + j * 16);
        }
        asm volatile("cp.async.commit_group;");
    };

    issue(0, dynb);
    issue(1, dynb + STAGE);

    uint32_t acc[2][8][2];                                // packed half2 x2
    #pragma unroll
    for (int i = 0; i < 2; i++)
        #pragma unroll
        for (int j = 0; j < 8; j++) { acc[i][j][0] = 0u; acc[i][j][1] = 0u; }

    for (int kc = 0; kc < NCHUNK; kc++) {
        if (kc < NCHUNK - 1) asm volatile("cp.async.wait_group 1;");
        else                 asm volatile("cp.async.wait_group 0;");
        __syncthreads();

        uint32_t sA = dynb + (kc & 1) * STAGE;
        uint32_t sB = sA + 16384;

        #pragma unroll
        for (int ks = 0; ks < 4; ks++) {
            const int k0 = ks * 32;                       // byte offset in row
            uint32_t a[2][4];
            #pragma unroll
            for (int mt = 0; mt < 2; mt++) {
                int arow = wm * 32 + mt * 16 + (g & 1) * 8 + rr;
                int acol = k0 + (g >> 1) * 16;
                ldm4(a[mt], sA + sw((uint32_t)(arow * 128 + acol)));
            }
            uint32_t b[8][2];
            #pragma unroll
            for (int ntp = 0; ntp < 4; ntp++) {
                int brow = wn * 64 + ntp * 16 + (g & 1) * 8 + rr;
                int bcol = k0 + (g >> 1) * 16;
                uint32_t t[4];
                ldm4(t, sB + sw((uint32_t)(brow * 128 + bcol)));
                b[2 * ntp][0] = t[0];     b[2 * ntp + 1][0] = t[1];
                b[2 * ntp][1] = t[2];     b[2 * ntp + 1][1] = t[3];
            }
            #pragma unroll
            for (int mt = 0; mt < 2; mt++)
                #pragma unroll
                for (int nt = 0; nt < 8; nt++)
                    mma_fp8h(acc[mt][nt], a[mt], b[nt]);
        }
        __syncthreads();
        if (kc + 2 < NCHUNK) issue(kc + 2, dynb + (kc & 1) * STAGE);
    }

    // ---- fused epilogue: logits = dot/128; streaming exp-sums ----
    const bool hasdiag = (bi == bj);
    const int mrow_loc = wm * 32 + (lane >> 2);
    const int ncol_loc = wn * 64 + 2 * (lane & 3);

    float rsum[2][2];
    rsum[0][0] = rsum[0][1] = rsum[1][0] = rsum[1][1] = 0.f;
    float dsum = 0.f;

    #pragma unroll
    for (int nt = 0; nt < 8; nt++) {
        float cs0 = 0.f, cs1 = 0.f;
        #pragma unroll
        for (int mt = 0; mt < 2; mt++) {
            float2 c01 = __half22float2(*(__half2*)&acc[mt][nt][0]);
            float2 c23 = __half22float2(*(__half2*)&acc[mt][nt][1]);
            float l00 = LSCALE * c01.x, l01 = LSCALE * c01.y;
            float l10 = LSCALE * c23.x, l11 = LSCALE * c23.y;
            float e00 = __expf(l00), e01 = __expf(l01);
            float e10 = __expf(l10), e11 = __expf(l11);
            rsum[mt][0] += e00 + e01;
            rsum[mt][1] += e10 + e11;
            cs0 += e00 + e10;
            cs1 += e01 + e11;
            if (hasdiag) {
                int m0 = mrow_loc + mt * 16;
                int n0 = ncol_loc + nt * 8;
                if (m0 == n0)         dsum += l00;
                if (m0 == n0 + 1)     dsum += l01;
                if (m0 + 8 == n0)     dsum += l10;
                if (m0 + 8 == n0 + 1) dsum += l11;
            }
        }
        #pragma unroll
        for (int o = 4; o < 32; o <<= 1) {
            cs0 += __shfl_xor_sync(0xffffffffu, cs0, o);
            cs1 += __shfl_xor_sync(0xffffffffu, cs1, o);
        }
        if (lane < 4) {
            int col = bj * 128 + wn * 64 + nt * 8 + 2 * lane;
            atomicAdd(&g_colsum[col],     cs0);
            atomicAdd(&g_colsum[col + 1], cs1);
        }
    }
    #pragma unroll
    for (int mt = 0; mt < 2; mt++) {
        #pragma unroll
        for (int h = 0; h < 2; h++) {
            float v = rsum[mt][h];
            v += __shfl_xor_sync(0xffffffffu, v, 1);
            v += __shfl_xor_sync(0xffffffffu, v, 2);
            if ((lane & 3) == 0) {
                int row = bi * 128 + wm * 32 + mt * 16 + h * 8 + (lane >> 2);
                atomicAdd(&g_rowsum[row], v);
            }
        }
    }
    if (hasdiag) {
        #pragma unroll
        for (int o = 16; o; o >>= 1) dsum += __shfl_xor_sync(0xffffffffu, dsum, o);
        if (lane == 0) atomicAdd(&g_diag, dsum);
    }
}

// ---------------------------------------------------------------------------
__global__ void finalize_kernel(float* out, int n) {
    float s = 0.f;
    for (int i = blockIdx.x * blockDim.x + threadIdx.x; i < n;
         i += gridDim.x * blockDim.x)
        s += logf(g_rowsum[i]) + logf(g_colsum[i]);
    #pragma unroll
    for (int o = 16; o; o >>= 1) s += __shfl_xor_sync(0xffffffffu, s, o);
    __shared__ float red[8];
    if ((threadIdx.x & 31) == 0) red[threadIdx.x >> 5] = s;
    __syncthreads();
    if (threadIdx.x == 0) {
        float v = 0.f;
        #pragma unroll
        for (int w = 0; w < 8; w++) v += red[w];
        atomicAdd(&g_part, v);
        __threadfence();
        unsigned t = atomicAdd(&g_cnt, 1u);
        if (t == gridDim.x - 1) {
            float tot = atomicAdd(&g_part, 0.f);
            out[0] = tot / (2.f * (float)n) - g_diag / (float)n;
        }
    }
}

// ---------------------------------------------------------------------------
extern "C" void kernel_launch(void* const* d_in, const int* in_sizes, int n_in,
                              void* d_out, int out_size) {
    const float* x = (const float*)d_in[0];
    const float* y = (const float*)d_in[1];
    int n = in_sizes[0] / D;   // 8192

    cudaFuncSetAttribute(gemm_kernel,
                         cudaFuncAttributeMaxDynamicSharedMemorySize, DYN_SMEM);

    normalize_kernel<<<(2 * n) / 16, 256>>>(x, y, n);  // 2 rows per warp
    gemm_kernel<<<dim3(n / 128, n / 128), 256, DYN_SMEM>>>();
    finalize_kernel<<<64, 256>>>((float*)d_out, n);
}